// round 15
// baseline (speedup 1.0000x reference)
#include <cuda_runtime.h>
#include <cuda_bf16.h>
#include <cstdint>

typedef unsigned long long u64;

#define B       32
#define TSTEPS  8
#define C1_OUT  64
#define H1      32
#define C2_OUT  128
#define H3      16
#define FC1_IN  8192
#define FC1_OUT 1024
#define FC2_OUT 10
#define ROWS    (TSTEPS * B)
#define KSPLIT  8
#define N1 (B * C1_OUT * H1 * H1)

#define K2 (C1_OUT * 9)
#define K3 (C2_OUT * 9)

__device__ float g_conv1out    [N1];
__device__ float g_s1t         [ROWS * C1_OUT * H1 * H1];
__device__ float g_conv2out_all[ROWS * C2_OUT * H1 * H1];
__device__ float g_s2p_all     [ROWS * C2_OUT * H3 * H3];
__device__ float g_conv3out_all[ROWS * C2_OUT * H3 * H3];
__device__ float g_s3p_all     [ROWS * FC1_IN];
__device__ float g_part        [KSPLIT * ROWS * FC1_OUT];
__device__ float g_sfc1_all    [ROWS * FC1_OUT];
__device__ float g_fc2out      [ROWS * FC2_OUT];
__device__ __nv_bfloat16 g_w2b [3 * K2 * 128];
__device__ __nv_bfloat16 g_w3b [3 * K3 * 128];
__device__ __nv_bfloat16 g_w1b [3 * FC1_OUT * FC1_IN];

__device__ __forceinline__ u64 pack2(float lo, float hi) {
    u64 r; asm("mov.b64 %0, {%1, %2};" : "=l"(r) : "f"(lo), "f"(hi)); return r;
}
__device__ __forceinline__ void ffma2(u64& acc, u64 a, u64 b) {
    asm("fma.rn.f32x2 %0, %1, %2, %0;" : "+l"(acc) : "l"(a), "l"(b));
}
__device__ __forceinline__ u64 add2(u64 a, u64 b) {
    u64 r; asm("add.rn.f32x2 %0, %1, %2;" : "=l"(r) : "l"(a), "l"(b)); return r;
}
__device__ __forceinline__ void cp_async4(uint32_t saddr, const void* gaddr, int srcsize) {
    asm volatile("cp.async.ca.shared.global [%0], [%1], 4, %2;"
                 :: "r"(saddr), "l"(gaddr), "r"(srcsize));
}
__device__ __forceinline__ void cp_async16(uint32_t saddr, const void* gaddr) {
    asm volatile("cp.async.ca.shared.global [%0], [%1], 16;"
                 :: "r"(saddr), "l"(gaddr));
}
__device__ __forceinline__ void cp_commit() { asm volatile("cp.async.commit_group;"); }
__device__ __forceinline__ void cp_wait0()  { asm volatile("cp.async.wait_group 0;"); }
__device__ __forceinline__ uint32_t smem_u32(const void* p) {
    return (uint32_t)__cvta_generic_to_shared(p);
}
__device__ __forceinline__ uint32_t bf2(float lo, float hi) {
    __nv_bfloat162 v = __floats2bfloat162_rn(lo, hi);
    return *(uint32_t*)&v;
}
__device__ __forceinline__ void split3(float v, float& s0, float& s1, float& s2) {
    __nv_bfloat16 b0 = __float2bfloat16(v);
    float r1 = v - __bfloat162float(b0);
    __nv_bfloat16 b1 = __float2bfloat16(r1);
    float r2 = r1 - __bfloat162float(b1);
    s0 = __bfloat162float(b0);
    s1 = __bfloat162float(b1);
    s2 = __bfloat162float(__float2bfloat16(r2));
}

// ======================================================================
// conv weight prep: exact 3-way bf16 split, layout [chunk][split][k16][oc128],
// chunk = kb*9 + tap (ic-block-major to match halo-reuse ordering).
// ======================================================================
template<int CIN>
__global__ void prep_w_bf16(const float* __restrict__ w, __nv_bfloat16* __restrict__ outp)
{
    int idx = blockIdx.x * 256 + threadIdx.x;
    if (idx >= CIN * 9 * 128) return;
    int oc = idx & 127;
    int k  = (idx >> 7) & 15;
    int c  = idx >> 11;
    int kb = c / 9, tap = c % 9;
    int ic = kb * 16 + k;

    float wv = w[((size_t)oc * CIN + ic) * 9 + tap];
    float s0, s1, s2;
    split3(wv, s0, s1, s2);

    size_t base = ((size_t)c * 3 * 16 + k) * 128 + oc;
    outp[base           ] = __float2bfloat16(s0);
    outp[base + 16 * 128] = __float2bfloat16(s1);
    outp[base + 32 * 128] = __float2bfloat16(s2);
}

// ======================================================================
// fc1 weight prep (coalesced, smem transpose).
// ======================================================================
__global__ void __launch_bounds__(256)
prep_fc1_bf16(const float* __restrict__ w, __nv_bfloat16* __restrict__ outp)
{
    __shared__ float tile[16][129];

    const int blk = blockIdx.x;
    const int ot  = blk >> 9;
    const int c   = blk & 511;
    const int tid = threadIdx.x;

#pragma unroll
    for (int j = 0; j < 2; ++j) {
        int s  = tid + j * 256;
        int oc = s >> 2;
        int kq = s & 3;
        float4 v = *(const float4*)&w[((size_t)(ot * 128 + oc)) * FC1_IN + c * 16 + kq * 4];
        tile[kq * 4 + 0][oc] = v.x;
        tile[kq * 4 + 1][oc] = v.y;
        tile[kq * 4 + 2][oc] = v.z;
        tile[kq * 4 + 3][oc] = v.w;
    }
    __syncthreads();

    uint32_t* outw = (uint32_t*)(outp + (size_t)blk * 3 * 16 * 128);
#pragma unroll
    for (int j = 0; j < 12; ++j) {
        int u   = tid + j * 256;
        int oc2 = u & 63;
        int k   = (u >> 6) & 15;
        int sp  = u >> 10;
        float a0, a1, a2, b0, b1, b2;
        split3(tile[k][oc2 * 2    ], a0, a1, a2);
        split3(tile[k][oc2 * 2 + 1], b0, b1, b2);
        float lo = (sp == 0) ? a0 : (sp == 1) ? a1 : a2;
        float hi = (sp == 0) ? b0 : (sp == 1) ? b1 : b2;
        outw[(sp * 16 + k) * 64 + oc2] = bf2(lo, hi);
    }
}

// ======================================================================
// MMA core
// ======================================================================
#define MMA_BF16(acc, a, b0v, b1v) \
    asm volatile( \
        "mma.sync.aligned.m16n8k16.row.col.f32.bf16.bf16.f32 " \
        "{%0,%1,%2,%3}, {%4,%5,%6,%7}, {%8,%9}, {%0,%1,%2,%3};" \
        : "+f"((acc)[0]), "+f"((acc)[1]), "+f"((acc)[2]), "+f"((acc)[3]) \
        : "r"((a)[0]), "r"((a)[1]), "r"((a)[2]), "r"((a)[3]), \
          "r"(b0v), "r"(b1v))

// ======================================================================
// Tensor-core conv with HALO A-reuse: stage a padded 16-ch halo tile once
// per ic-block; all 9 taps read shifted ldmatrix windows from it.
// Inner MMA / B pipeline / warp tiling identical to the proven R8 shape.
// CTA: 128 pixels x 128 oc, 8 warps (warp = 32 pix x 64 oc).
// ======================================================================
template<int CIN, int HW>
__global__ void __launch_bounds__(256)
conv_mma_kernel(const float* __restrict__ in,
                const __nv_bfloat16* __restrict__ wprep,
                const float* __restrict__ bias,
                float* __restrict__ out)
{
    constexpr int NPIX  = HW * HW;
    constexpr int KB    = CIN / 16;
    constexpr int NCH   = KB * 9;
    constexpr int TROWS = 128 / HW;          // image rows per tile: 4 (HW=32) / 8 (HW=16)
    constexpr int HROWS = TROWS + 2;         // halo rows: 6 / 10
    constexpr int HCOLS = HW + 2;            // 34 / 18
    constexpr int NCELL = HROWS * HCOLS;     // 204 / 180
    constexpr int CSTR  = 24;                // bf16 units per cell (48B: 32 data + 16 pad)

    __shared__ __align__(16) __nv_bfloat16 halo[NCELL * CSTR];
    __shared__ __nv_bfloat16 B_s[2][3][16][136];

    const int tid  = threadIdx.x;
    const int wid  = tid >> 5;
    const int lane = tid & 31;
    const int tile = blockIdx.x;
    const int img  = blockIdx.y;
    const int wp   = (wid & 3) * 32;
    const int wo   = (wid >> 2) * 64;

    const float* inimg = in + (size_t)img * CIN * NPIX;
    const int row0 = tile * TROWS;

    float acc[2][8][4];
#pragma unroll
    for (int i = 0; i < 2; ++i)
#pragma unroll
        for (int j = 0; j < 8; ++j)
#pragma unroll
            for (int q = 0; q < 4; ++q) acc[i][j][q] = 0.f;

    auto stage_halo = [&](int kb) {
        constexpr int TOT = NCELL * 16;
#pragma unroll
        for (int j = 0; j < (TOT + 255) / 256; ++j) {
            int idx = tid + j * 256;
            if (idx < TOT) {
                int ch   = idx / NCELL;
                int cell = idx - ch * NCELL;
                int r    = cell / HCOLS;
                int cl   = cell - r * HCOLS;
                int gy   = row0 - 1 + r;
                int gx   = cl - 1;
                bool ok  = (gy >= 0) & (gy < HW) & (gx >= 0) & (gx < HW);
                float v  = ok ? inimg[(size_t)(kb * 16 + ch) * NPIX + gy * HW + gx] : 0.f;
                halo[cell * CSTR + ch] = __float2bfloat16(v);
            }
        }
    };
    auto stageB = [&](int c, int buf) {
        const __nv_bfloat16* base = wprep + (size_t)c * 3 * 16 * 128;
#pragma unroll
        for (int rep = 0; rep < 3; ++rep) {
            int idx = tid + rep * 256;
            int row = idx >> 4;
            int seg = idx & 15;
            int sp = row >> 4, k = row & 15;
            uint32_t d = smem_u32(&B_s[buf][sp][k][seg * 8]);
            cp_async16(d, base + ((size_t)row * 128 + seg * 8));
        }
    };

    const uint32_t halo_base = smem_u32(halo);

    auto mma_chunk = [&](int tap, int buf) {
        const int dy = tap / 3, dx = tap % 3;   // 0..2 == offset -1..1 relative to halo
        uint32_t a[2][4];
#pragma unroll
        for (int f = 0; f < 2; ++f) {
            int lrow, col;
            if (HW == 32) { lrow = (wid & 3) + dy;            col = f * 16 + (lane & 15) + dx; }
            else          { lrow = (wid & 3) * 2 + f + dy;    col = (lane & 15) + dx; }
            uint32_t addr = halo_base + (uint32_t)(lrow * HCOLS + col) * 48u + ((lane >> 4) << 4);
            asm volatile("ldmatrix.sync.aligned.m8n8.x4.shared.b16 {%0,%1,%2,%3}, [%4];"
                         : "=r"(a[f][0]), "=r"(a[f][1]), "=r"(a[f][2]), "=r"(a[f][3])
                         : "r"(addr));
        }
#pragma unroll
        for (int sp = 0; sp < 3; ++sp) {
#pragma unroll
            for (int og = 0; og < 4; ++og) {
                uint32_t baddr = smem_u32(&B_s[buf][sp][lane & 15][wo + og * 16 + ((lane >> 4) << 3)]);
                uint32_t b0, b1, b2, b3;
                asm volatile("ldmatrix.sync.aligned.m8n8.x4.trans.shared.b16 {%0,%1,%2,%3}, [%4];"
                             : "=r"(b0), "=r"(b1), "=r"(b2), "=r"(b3) : "r"(baddr));
#pragma unroll
                for (int f = 0; f < 2; ++f) {
                    MMA_BF16(acc[f][og * 2    ], a[f], b0, b1);
                    MMA_BF16(acc[f][og * 2 + 1], a[f], b2, b3);
                }
            }
        }
    };

    // prologue
    stageB(0, 0); cp_commit();
    stage_halo(0);
    cp_wait0();
    __syncthreads();

    for (int c = 0; c < NCH; ++c) {
        int buf = c & 1;
        if (c + 1 < NCH) {
            stageB(c + 1, buf ^ 1); cp_commit();
        }
        mma_chunk(c % 9, buf);
        if (c + 1 < NCH) {
            cp_wait0();
            if ((c + 1) % 9 == 0) {
                __syncthreads();                 // all warps done reading current halo
                stage_halo((c + 1) / 9);
            }
        }
        __syncthreads();
    }

    const int q  = lane >> 2;
    const int cc = (lane & 3) * 2;
    float* outimg = out + (size_t)img * C2_OUT * NPIX;
#pragma unroll
    for (int f = 0; f < 2; ++f) {
        int pix = tile * 128 + wp + f * 16 + q;
#pragma unroll
        for (int of = 0; of < 8; ++of) {
            int oc = wo + of * 8 + cc;
            float bv0 = bias[oc], bv1 = bias[oc + 1];
            outimg[(size_t)oc * NPIX + pix]           = acc[f][of][0] + bv0;
            outimg[(size_t)(oc + 1) * NPIX + pix]     = acc[f][of][1] + bv1;
            outimg[(size_t)oc * NPIX + pix + 8]       = acc[f][of][2] + bv0;
            outimg[(size_t)(oc + 1) * NPIX + pix + 8] = acc[f][of][3] + bv1;
        }
    }
}

// ======================================================================
// fc1 GEMM via mma.sync bf16 — R8 known-good shape (unchanged).
// ======================================================================
__global__ void __launch_bounds__(256)
fc1_mma_kernel(const __nv_bfloat16* __restrict__ wprep)
{
    constexpr int NCH = 64;

    __shared__ __nv_bfloat16 A_s[2][128][24];
    __shared__ __nv_bfloat16 B_s[2][3][16][136];

    const int tid  = threadIdx.x;
    const int wid  = tid >> 5;
    const int lane = tid & 31;
    const int ot   = blockIdx.x;
    const int rt   = blockIdx.y;
    const int ks   = blockIdx.z;
    const int wp   = (wid & 3) * 32;
    const int wo   = (wid >> 2) * 64;

    const int p    = tid >> 1;
    const int half = tid & 1;
    const int row  = rt * 128 + p;

    float acc[2][8][4];
#pragma unroll
    for (int i = 0; i < 2; ++i)
#pragma unroll
        for (int j = 0; j < 8; ++j)
#pragma unroll
            for (int q = 0; q < 4; ++q) acc[i][j][q] = 0.f;

    auto ldgA = [&](int c, float* r) {
        const float* src = &g_s3p_all[(size_t)row * FC1_IN + (ks * NCH + c) * 16 + half * 8];
        float4 v0 = *(const float4*)src;
        float4 v1 = *(const float4*)(src + 4);
        r[0] = v0.x; r[1] = v0.y; r[2] = v0.z; r[3] = v0.w;
        r[4] = v1.x; r[5] = v1.y; r[6] = v1.z; r[7] = v1.w;
    };
    auto stsA = [&](const float* r, int buf) {
        uint4 v;
        v.x = bf2(r[0], r[1]); v.y = bf2(r[2], r[3]);
        v.z = bf2(r[4], r[5]); v.w = bf2(r[6], r[7]);
        *(uint4*)&A_s[buf][p][half * 8] = v;
    };
    auto stageB = [&](int c, int buf) {
        const __nv_bfloat16* base = wprep + (size_t)(ot * 512 + ks * NCH + c) * 3 * 16 * 128;
#pragma unroll
        for (int rep = 0; rep < 3; ++rep) {
            int idx = tid + rep * 256;
            int rowk = idx >> 4;
            int seg  = idx & 15;
            int sp = rowk >> 4, k = rowk & 15;
            uint32_t d = smem_u32(&B_s[buf][sp][k][seg * 8]);
            cp_async16(d, base + ((size_t)rowk * 128 + seg * 8));
        }
    };

    auto mma_chunk = [&](int buf) {
        uint32_t a[2][4];
#pragma unroll
        for (int f = 0; f < 2; ++f) {
            uint32_t addr = smem_u32(&A_s[buf][wp + f * 16 + (lane & 15)][(lane >> 4) * 8]);
            asm volatile("ldmatrix.sync.aligned.m8n8.x4.shared.b16 {%0,%1,%2,%3}, [%4];"
                         : "=r"(a[f][0]), "=r"(a[f][1]), "=r"(a[f][2]), "=r"(a[f][3])
                         : "r"(addr));
        }
#pragma unroll
        for (int sp = 0; sp < 3; ++sp) {
#pragma unroll
            for (int og = 0; og < 4; ++og) {
                uint32_t baddr = smem_u32(&B_s[buf][sp][lane & 15][wo + og * 16 + ((lane >> 4) << 3)]);
                uint32_t b0, b1, b2, b3;
                asm volatile("ldmatrix.sync.aligned.m8n8.x4.trans.shared.b16 {%0,%1,%2,%3}, [%4];"
                             : "=r"(b0), "=r"(b1), "=r"(b2), "=r"(b3) : "r"(baddr));
#pragma unroll
                for (int f = 0; f < 2; ++f) {
                    MMA_BF16(acc[f][og * 2    ], a[f], b0, b1);
                    MMA_BF16(acc[f][og * 2 + 1], a[f], b2, b3);
                }
            }
        }
    };

    float ar[8];
    stageB(0, 0); cp_commit();
    ldgA(0, ar);
    stsA(ar, 0);
    cp_wait0();
    __syncthreads();

    for (int c = 0; c < NCH; ++c) {
        int buf = c & 1;
        if (c + 1 < NCH) {
            stageB(c + 1, buf ^ 1); cp_commit();
            ldgA(c + 1, ar);
        }
        mma_chunk(buf);
        if (c + 1 < NCH) {
            stsA(ar, buf ^ 1);
            cp_wait0();
        }
        __syncthreads();
    }

    const int q  = lane >> 2;
    const int cc = (lane & 3) * 2;
#pragma unroll
    for (int f = 0; f < 2; ++f) {
        int r0 = rt * 128 + wp + f * 16 + q;
#pragma unroll
        for (int of = 0; of < 8; ++of) {
            int o = ot * 128 + wo + of * 8 + cc;
            g_part[((size_t)ks * ROWS + r0    ) * FC1_OUT + o    ] = acc[f][of][0];
            g_part[((size_t)ks * ROWS + r0    ) * FC1_OUT + o + 1] = acc[f][of][1];
            g_part[((size_t)ks * ROWS + r0 + 8) * FC1_OUT + o    ] = acc[f][of][2];
            g_part[((size_t)ks * ROWS + r0 + 8) * FC1_OUT + o + 1] = acc[f][of][3];
        }
    }
}

// ======================================================================
// conv1 (tiny, 3 input ch): FFMA2 pipelined conv
// ======================================================================
template<int CIN, int HW, int GB, int ICB>
__global__ void __launch_bounds__(GB*(HW/2)*(HW/2))
conv3x3_pipe(const float* __restrict__ in,
             const float* __restrict__ wt,
             const float* __restrict__ bias,
             float* __restrict__ out,
             int Cout)
{
    constexpr int TP    = HW / 2;
    constexpr int TSUB  = TP * TP;
    constexpr int NT    = GB * TSUB;
    constexpr int TW    = HW + 2;
    constexpr int TS    = TW * TW;
    constexpr int OCT   = 8;
    constexpr int NST   = CIN / ICB;
    constexpr int LSLOT = (TS + TSUB - 1) / TSUB;
    constexpr int WTOT  = ICB * OCT * 9;
    constexpr int WSLOT = (WTOT + NT - 1) / NT;

    __shared__ float tile[2][ICB][GB][TS];
    __shared__ u64   ws  [2][ICB][OCT * 9];

    const int tid = threadIdx.x;
    const int sub = tid / TSUB;
    const int st  = tid % TSUB;
    const int b   = blockIdx.y * GB + sub;
    const int ocb = blockIdx.x * OCT;
    const int ty  = (st / TP) * 2;
    const int tx  = (st % TP) * 2;

    const float* inb = in + (size_t)b * CIN * HW * HW;

    int l_soff[LSLOT], l_goff[LSLOT], l_size[LSLOT];
#pragma unroll
    for (int k = 0; k < LSLOT; ++k) {
        int i = st + k * TSUB;
        int r = i / TW - 1, c = i % TW - 1;
        bool live = (i < TS);
        bool inb_ = live && r >= 0 && r < HW && c >= 0 && c < HW;
        l_soff[k] = live ? i : -1;
        l_goff[k] = inb_ ? (r * HW + c) : 0;
        l_size[k] = inb_ ? 4 : 0;
    }

    float wreg[WSLOT];

    auto issue_loads = [&](int s, int buf) {
#pragma unroll
        for (int ic = 0; ic < ICB; ++ic) {
            const float* src = inb + (size_t)(s * ICB + ic) * HW * HW;
#pragma unroll
            for (int k = 0; k < LSLOT; ++k) {
                if (l_soff[k] >= 0) {
                    uint32_t d = smem_u32(&tile[buf][ic][sub][l_soff[k]]);
                    cp_async4(d, src + l_goff[k], l_size[k]);
                }
            }
        }
    };
    auto load_w = [&](int s) {
#pragma unroll
        for (int j = 0; j < WSLOT; ++j) {
            int i = tid + j * NT;
            if (i < WTOT) {
                int ic = i / (OCT * 9), rem = i % (OCT * 9);
                int o = rem / 9, k = rem % 9;
                wreg[j] = wt[((size_t)(ocb + o) * CIN + s * ICB + ic) * 9 + k];
            }
        }
    };
    auto store_w = [&](int buf) {
#pragma unroll
        for (int j = 0; j < WSLOT; ++j) {
            int i = tid + j * NT;
            if (i < WTOT) {
                int ic = i / (OCT * 9), rem = i % (OCT * 9);
                ws[buf][ic][rem] = pack2(wreg[j], wreg[j]);
            }
        }
    };

    u64 pa[OCT][2];
#pragma unroll
    for (int o = 0; o < OCT; ++o) { pa[o][0] = 0ull; pa[o][1] = 0ull; }

    auto compute = [&](int buf) {
#pragma unroll
        for (int ic = 0; ic < ICB; ++ic) {
            const float* tp = &tile[buf][ic][sub][0];
            float r[4][4];
#pragma unroll
            for (int dy = 0; dy < 4; ++dy)
#pragma unroll
                for (int dx = 0; dx < 4; ++dx)
                    r[dy][dx] = tp[(ty + dy) * TW + tx + dx];
            u64 pr[4][3];
#pragma unroll
            for (int dy = 0; dy < 4; ++dy)
#pragma unroll
                for (int kx = 0; kx < 3; ++kx)
                    pr[dy][kx] = pack2(r[dy][kx], r[dy][kx + 1]);
#pragma unroll
            for (int o = 0; o < OCT; ++o) {
                const u64* w9 = &ws[buf][ic][o * 9];
#pragma unroll
                for (int ky = 0; ky < 3; ++ky) {
                    u64 w0 = w9[ky * 3 + 0], w1 = w9[ky * 3 + 1], w2 = w9[ky * 3 + 2];
                    ffma2(pa[o][0], pr[ky    ][0], w0);
                    ffma2(pa[o][0], pr[ky    ][1], w1);
                    ffma2(pa[o][0], pr[ky    ][2], w2);
                    ffma2(pa[o][1], pr[ky + 1][0], w0);
                    ffma2(pa[o][1], pr[ky + 1][1], w1);
                    ffma2(pa[o][1], pr[ky + 1][2], w2);
                }
            }
        }
    };

    load_w(0); store_w(0);
    issue_loads(0, 0);
    cp_commit(); cp_wait0();
    __syncthreads();

#pragma unroll 2
    for (int s = 0; s < NST; ++s) {
        int buf = s & 1;
        if (s + 1 < NST) { issue_loads(s + 1, buf ^ 1); cp_commit(); load_w(s + 1); }
        compute(buf);
        if (s + 1 < NST) { cp_wait0(); store_w(buf ^ 1); }
        __syncthreads();
    }

#pragma unroll
    for (int o = 0; o < OCT; ++o) {
        float bv = bias[ocb + o];
        u64 bp = pack2(bv, bv);
        u64 r0 = add2(pa[o][0], bp);
        u64 r1 = add2(pa[o][1], bp);
        float* dst = out + (((size_t)b * Cout + ocb + o) * HW + ty) * HW + tx;
        *(u64*)(dst)      = r0;
        *(u64*)(dst + HW) = r1;
    }
}

// ---------------- LIF / pool / fc kernels ----------------
__global__ void lif1_all_kernel(const float* __restrict__ mask_f1)
{
    int i = blockIdx.x * blockDim.x + threadIdx.x;
    if (i >= N1) return;
    float x = g_conv1out[i];
    float mk = mask_f1[i];
    float m = 0.f;
#pragma unroll
    for (int t = 0; t < TSTEPS; ++t) {
        m += x;
        float sp = (m >= 1.f) ? 1.f : 0.f;
        m -= sp;
        g_s1t[(size_t)t * N1 + i] = sp * mk;
    }
}

__global__ void lif2pool_all_kernel()
{
    int idx = blockIdx.x * blockDim.x + threadIdx.x;
    if (idx >= B * C2_OUT * H3 * H3) return;
    int px = idx & 15;
    int py = (idx >> 4) & 15;
    int c  = (idx >> 8) & 127;
    int b  = idx >> 15;
    const size_t chanstride = (size_t)B * C2_OUT * H1 * H1;
    size_t base  = ((size_t)b * C2_OUT + c) * (H1 * H1) + (2 * py) * H1 + 2 * px;
    size_t obase = ((size_t)b * C2_OUT + c) * (H3 * H3) + py * H3 + px;
    float m0 = 0.f, m1 = 0.f, m2v = 0.f, m3v = 0.f;
#pragma unroll
    for (int t = 0; t < TSTEPS; ++t) {
        float2 a  = *(const float2*)&g_conv2out_all[base + (size_t)t * chanstride];
        float2 bq = *(const float2*)&g_conv2out_all[base + H1 + (size_t)t * chanstride];
        m0 += a.x;   float s0 = (m0 >= 1.f) ? 1.f : 0.f;  m0 -= s0;
        m1 += a.y;   float s1 = (m1 >= 1.f) ? 1.f : 0.f;  m1 -= s1;
        m2v += bq.x; float s2 = (m2v >= 1.f) ? 1.f : 0.f; m2v -= s2;
        m3v += bq.y; float s3 = (m3v >= 1.f) ? 1.f : 0.f; m3v -= s3;
        g_s2p_all[obase + (size_t)t * (B * C2_OUT * H3 * H3)] = (s0 + s1 + s2 + s3) * 0.25f;
    }
}

__global__ void lif3maskpool_all_kernel(const float* __restrict__ mask_f2)
{
    int idx = blockIdx.x * blockDim.x + threadIdx.x;
    if (idx >= B * C2_OUT * 8 * 8) return;
    int px = idx & 7;
    int py = (idx >> 3) & 7;
    int c  = (idx >> 6) & 127;
    int b  = idx >> 13;
    const size_t slab = (size_t)B * C2_OUT * H3 * H3;
    size_t base  = ((size_t)b * C2_OUT + c) * (H3 * H3) + (2 * py) * H3 + 2 * px;
    size_t obase = ((size_t)b * C2_OUT + c) * 64 + py * 8 + px;
    float2 mka = *(const float2*)&mask_f2[base];
    float2 mkb = *(const float2*)&mask_f2[base + H3];
    float m0 = 0.f, m1 = 0.f, m2v = 0.f, m3v = 0.f;
#pragma unroll
    for (int t = 0; t < TSTEPS; ++t) {
        float2 a  = *(const float2*)&g_conv3out_all[base + (size_t)t * slab];
        float2 bq = *(const float2*)&g_conv3out_all[base + H3 + (size_t)t * slab];
        m0 += a.x;   float s0 = (m0 >= 1.f) ? 1.f : 0.f;  m0 -= s0;
        m1 += a.y;   float s1 = (m1 >= 1.f) ? 1.f : 0.f;  m1 -= s1;
        m2v += bq.x; float s2 = (m2v >= 1.f) ? 1.f : 0.f; m2v -= s2;
        m3v += bq.y; float s3 = (m3v >= 1.f) ? 1.f : 0.f; m3v -= s3;
        g_s3p_all[obase + (size_t)t * (B * FC1_IN)] =
            (s0 * mka.x + s1 * mka.y + s2 * mkb.x + s3 * mkb.y) * 0.25f;
    }
}

__global__ void fc1_chain_kernel(const float* __restrict__ fc1_b,
                                 const float* __restrict__ mask_c1)
{
    int idx = blockIdx.x * blockDim.x + threadIdx.x;
    if (idx >= B * FC1_OUT) return;
    int b = idx >> 10, o = idx & 1023;
    float mk = mask_c1[idx];
    float bias = fc1_b[o];
    float m = 0.f;
#pragma unroll
    for (int t = 0; t < TSTEPS; ++t) {
        int row = t * B + b;
        float sum = bias;
#pragma unroll
        for (int ks = 0; ks < KSPLIT; ++ks)
            sum += g_part[((size_t)ks * ROWS + row) * FC1_OUT + o];
        m += sum;
        float sp = (m >= 1.f) ? 1.f : 0.f;
        m -= sp;
        g_sfc1_all[(size_t)row * FC1_OUT + o] = sp * mk;
    }
}

__global__ void fc2_all_kernel(const float* __restrict__ w)
{
    int gw   = (blockIdx.x * blockDim.x + threadIdx.x) >> 5;
    int lane = threadIdx.x & 31;
    if (gw >= ROWS * FC2_OUT) return;
    int row = gw / FC2_OUT, o = gw % FC2_OUT;
    const float* sr = g_sfc1_all + (size_t)row * FC1_OUT;
    const float* wr = w + (size_t)o * FC1_OUT;
    float acc = 0.f;
#pragma unroll 8
    for (int k = lane; k < FC1_OUT; k += 32)
        acc += sr[k] * wr[k];
#pragma unroll
    for (int off = 16; off; off >>= 1)
        acc += __shfl_down_sync(0xFFFFFFFFu, acc, off);
    if (lane == 0)
        g_fc2out[row * FC2_OUT + o] = acc;
}

__global__ void fc2_chain_kernel(const float* __restrict__ fc2_b,
                                 float* __restrict__ c2)
{
    int idx = threadIdx.x;
    if (idx >= B * FC2_OUT) return;
    int b = idx / FC2_OUT, o = idx % FC2_OUT;
    float bias = fc2_b[o];
    float m = 0.f;
#pragma unroll
    for (int t = 0; t < TSTEPS; ++t) {
        m += g_fc2out[(t * B + b) * FC2_OUT + o] + bias;
        float sp = (m >= 1.f) ? 1.f : 0.f;
        m -= sp;
    }
    c2[idx] = m;
}

// ---------------- host launcher ----------------
extern "C" void kernel_launch(void* const* d_in, const int* in_sizes, int n_in,
                              void* d_out, int out_size)
{
    const float* X       = (const float*)d_in[0];
    const float* conv1_w = (const float*)d_in[1];
    const float* conv1_b = (const float*)d_in[2];
    const float* conv2_w = (const float*)d_in[3];
    const float* conv2_b = (const float*)d_in[4];
    const float* conv3_w = (const float*)d_in[5];
    const float* conv3_b = (const float*)d_in[6];
    const float* fc1_w   = (const float*)d_in[7];
    const float* fc1_b   = (const float*)d_in[8];
    const float* fc2_w   = (const float*)d_in[9];
    const float* fc2_b   = (const float*)d_in[10];
    const float* mask_f1 = (const float*)d_in[11];
    const float* mask_f2 = (const float*)d_in[12];
    const float* mask_c1 = (const float*)d_in[13];

    float* c2 = (float*)d_out;

    float *conv1out, *s1t, *conv2out, *s2p, *conv3out;
    __nv_bfloat16 *w2b, *w3b, *w1b;
    cudaGetSymbolAddress((void**)&conv1out, g_conv1out);
    cudaGetSymbolAddress((void**)&s1t,      g_s1t);
    cudaGetSymbolAddress((void**)&conv2out, g_conv2out_all);
    cudaGetSymbolAddress((void**)&s2p,      g_s2p_all);
    cudaGetSymbolAddress((void**)&conv3out, g_conv3out_all);
    cudaGetSymbolAddress((void**)&w2b,      g_w2b);
    cudaGetSymbolAddress((void**)&w3b,      g_w3b);
    cudaGetSymbolAddress((void**)&w1b,      g_w1b);

    // weight preps
    prep_w_bf16<C1_OUT><<<(C1_OUT * 9 * 128 + 255) / 256, 256>>>(conv2_w, w2b);
    prep_w_bf16<C2_OUT><<<(C2_OUT * 9 * 128 + 255) / 256, 256>>>(conv3_w, w3b);
    prep_fc1_bf16<<<8 * 512, 256>>>(fc1_w, w1b);

    // layer 1: conv once, LIF over all timesteps once
    conv3x3_pipe<3, H1, 1, 1><<<dim3(C1_OUT / 8, B), 256>>>(X, conv1_w, conv1_b, conv1out, C1_OUT);
    lif1_all_kernel<<<(N1 + 255) / 256, 256>>>(mask_f1);

    // layer 2: tensor-core conv with halo A-reuse
    conv_mma_kernel<C1_OUT, H1><<<dim3(8, ROWS), 256>>>(s1t, w2b, conv2_b, conv2out);
    lif2pool_all_kernel<<<(B * C2_OUT * H3 * H3 + 255) / 256, 256>>>();

    // layer 3: tensor-core conv with halo A-reuse
    conv_mma_kernel<C2_OUT, H3><<<dim3(2, ROWS), 256>>>(s2p, w3b, conv3_b, conv3out);
    lif3maskpool_all_kernel<<<(B * C2_OUT * 8 * 8 + 255) / 256, 256>>>(mask_f2);

    // fc1 + fc2
    fc1_mma_kernel<<<dim3(8, 2, KSPLIT), 256>>>(w1b);
    fc1_chain_kernel<<<(B * FC1_OUT + 255) / 256, 256>>>(fc1_b, mask_c1);
    fc2_all_kernel<<<(ROWS * FC2_OUT * 32 + 255) / 256, 256>>>(fc2_w);
    fc2_chain_kernel<<<1, 512>>>(fc2_b, c2);
}

// round 16
// speedup vs baseline: 1.0845x; 1.0845x over previous
#include <cuda_runtime.h>
#include <cuda_bf16.h>
#include <cstdint>

typedef unsigned long long u64;

#define B       32
#define TSTEPS  8
#define C1_OUT  64
#define H1      32
#define C2_OUT  128
#define H3      16
#define FC1_IN  8192
#define FC1_OUT 1024
#define FC2_OUT 10
#define ROWS    (TSTEPS * B)
#define KSPLIT  16
#define N1 (B * C1_OUT * H1 * H1)

#define K2 (C1_OUT * 9)
#define K3 (C2_OUT * 9)

__device__ float g_conv1out    [N1];
__device__ float g_s1t         [ROWS * C1_OUT * H1 * H1];
__device__ float g_conv2out_all[ROWS * C2_OUT * H1 * H1];
__device__ float g_s2p_all     [ROWS * C2_OUT * H3 * H3];
__device__ float g_conv3out_all[ROWS * C2_OUT * H3 * H3];
__device__ float g_s3p_all     [ROWS * FC1_IN];
__device__ float g_part        [KSPLIT * ROWS * FC1_OUT];
__device__ float g_sfc1_all    [ROWS * FC1_OUT];
__device__ float g_fc2out      [ROWS * FC2_OUT];
__device__ __nv_bfloat16 g_w2b [3 * K2 * 128];
__device__ __nv_bfloat16 g_w3b [3 * K3 * 128];
__device__ __nv_bfloat16 g_w1b [3 * FC1_OUT * FC1_IN];

__device__ __forceinline__ u64 pack2(float lo, float hi) {
    u64 r; asm("mov.b64 %0, {%1, %2};" : "=l"(r) : "f"(lo), "f"(hi)); return r;
}
__device__ __forceinline__ void ffma2(u64& acc, u64 a, u64 b) {
    asm("fma.rn.f32x2 %0, %1, %2, %0;" : "+l"(acc) : "l"(a), "l"(b));
}
__device__ __forceinline__ u64 add2(u64 a, u64 b) {
    u64 r; asm("add.rn.f32x2 %0, %1, %2;" : "=l"(r) : "l"(a), "l"(b)); return r;
}
__device__ __forceinline__ void cp_async4(uint32_t saddr, const void* gaddr, int srcsize) {
    asm volatile("cp.async.ca.shared.global [%0], [%1], 4, %2;"
                 :: "r"(saddr), "l"(gaddr), "r"(srcsize));
}
__device__ __forceinline__ void cp_async16(uint32_t saddr, const void* gaddr) {
    asm volatile("cp.async.ca.shared.global [%0], [%1], 16;"
                 :: "r"(saddr), "l"(gaddr));
}
__device__ __forceinline__ void cp_commit() { asm volatile("cp.async.commit_group;"); }
__device__ __forceinline__ void cp_wait0()  { asm volatile("cp.async.wait_group 0;"); }
__device__ __forceinline__ uint32_t smem_u32(const void* p) {
    return (uint32_t)__cvta_generic_to_shared(p);
}
__device__ __forceinline__ uint32_t bf2(float lo, float hi) {
    __nv_bfloat162 v = __floats2bfloat162_rn(lo, hi);
    return *(uint32_t*)&v;
}
__device__ __forceinline__ void split3(float v, float& s0, float& s1, float& s2) {
    __nv_bfloat16 b0 = __float2bfloat16(v);
    float r1 = v - __bfloat162float(b0);
    __nv_bfloat16 b1 = __float2bfloat16(r1);
    float r2 = r1 - __bfloat162float(b1);
    s0 = __bfloat162float(b0);
    s1 = __bfloat162float(b1);
    s2 = __bfloat162float(__float2bfloat16(r2));
}

// ======================================================================
// conv weight prep: exact 3-way bf16 split, layout [chunk][split][k16][oc128].
// ======================================================================
template<int CIN>
__global__ void prep_w_bf16(const float* __restrict__ w, __nv_bfloat16* __restrict__ outp)
{
    constexpr int KB = CIN / 16;
    int idx = blockIdx.x * 256 + threadIdx.x;
    if (idx >= CIN * 9 * 128) return;
    int oc = idx & 127;
    int k  = (idx >> 7) & 15;
    int c  = idx >> 11;
    int tap = c / KB, kb = c % KB;
    int ic  = kb * 16 + k;

    float wv = w[((size_t)oc * CIN + ic) * 9 + tap];
    float s0, s1, s2;
    split3(wv, s0, s1, s2);

    size_t base = ((size_t)c * 3 * 16 + k) * 128 + oc;
    outp[base           ] = __float2bfloat16(s0);
    outp[base + 16 * 128] = __float2bfloat16(s1);
    outp[base + 32 * 128] = __float2bfloat16(s2);
}

// ======================================================================
// fc1 weight prep (coalesced, smem transpose).
// ======================================================================
__global__ void __launch_bounds__(256)
prep_fc1_bf16(const float* __restrict__ w, __nv_bfloat16* __restrict__ outp)
{
    __shared__ float tile[16][129];

    const int blk = blockIdx.x;
    const int ot  = blk >> 9;
    const int c   = blk & 511;
    const int tid = threadIdx.x;

#pragma unroll
    for (int j = 0; j < 2; ++j) {
        int s  = tid + j * 256;
        int oc = s >> 2;
        int kq = s & 3;
        float4 v = *(const float4*)&w[((size_t)(ot * 128 + oc)) * FC1_IN + c * 16 + kq * 4];
        tile[kq * 4 + 0][oc] = v.x;
        tile[kq * 4 + 1][oc] = v.y;
        tile[kq * 4 + 2][oc] = v.z;
        tile[kq * 4 + 3][oc] = v.w;
    }
    __syncthreads();

    uint32_t* outw = (uint32_t*)(outp + (size_t)blk * 3 * 16 * 128);
#pragma unroll
    for (int j = 0; j < 12; ++j) {
        int u   = tid + j * 256;
        int oc2 = u & 63;
        int k   = (u >> 6) & 15;
        int sp  = u >> 10;
        float a0, a1, a2, b0, b1, b2;
        split3(tile[k][oc2 * 2    ], a0, a1, a2);
        split3(tile[k][oc2 * 2 + 1], b0, b1, b2);
        float lo = (sp == 0) ? a0 : (sp == 1) ? a1 : a2;
        float hi = (sp == 0) ? b0 : (sp == 1) ? b1 : b2;
        outw[(sp * 16 + k) * 64 + oc2] = bf2(lo, hi);
    }
}

// ======================================================================
// MMA core
// ======================================================================
#define MMA_BF16(acc, a, b0v, b1v) \
    asm volatile( \
        "mma.sync.aligned.m16n8k16.row.col.f32.bf16.bf16.f32 " \
        "{%0,%1,%2,%3}, {%4,%5,%6,%7}, {%8,%9}, {%0,%1,%2,%3};" \
        : "+f"((acc)[0]), "+f"((acc)[1]), "+f"((acc)[2]), "+f"((acc)[3]) \
        : "r"((a)[0]), "r"((a)[1]), "r"((a)[2]), "r"((a)[3]), \
          "r"(b0v), "r"(b1v))

// ======================================================================
// Tensor-core conv via mma.sync bf16 (exact 3-split) — R8 known-good shape.
// CTA: 128 pixels x 128 oc, 8 warps (warp = 32 pix x 64 oc).
// ======================================================================
template<int CIN, int HW>
__global__ void __launch_bounds__(256)
conv_mma_kernel(const float* __restrict__ in,
                const __nv_bfloat16* __restrict__ wprep,
                const float* __restrict__ bias,
                float* __restrict__ out)
{
    constexpr int NPIX = HW * HW;
    constexpr int KB   = CIN / 16;
    constexpr int NCH  = KB * 9;

    __shared__ __nv_bfloat16 A_s[2][128][24];
    __shared__ __nv_bfloat16 B_s[2][3][16][136];

    const int tid  = threadIdx.x;
    const int wid  = tid >> 5;
    const int lane = tid & 31;
    const int tile = blockIdx.x;
    const int img  = blockIdx.y;
    const int wp   = (wid & 3) * 32;
    const int wo   = (wid >> 2) * 64;

    const float* inimg = in + (size_t)img * CIN * NPIX;

    const int p    = tid >> 1;
    const int half = tid & 1;
    const int g    = tile * 128 + p;
    const int py   = g / HW;
    const int px   = g % HW;

    float acc[2][8][4];
#pragma unroll
    for (int i = 0; i < 2; ++i)
#pragma unroll
        for (int j = 0; j < 8; ++j)
#pragma unroll
            for (int q = 0; q < 4; ++q) acc[i][j][q] = 0.f;

    auto ldgA = [&](int c, float* r) {
        int tap = c / KB, kb = c % KB;
        int ky = tap / 3 - 1, kx = tap % 3 - 1;
        int iy = py + ky, ix = px + kx;
        bool ok = (iy >= 0) & (iy < HW) & (ix >= 0) & (ix < HW);
        const float* src = inimg + (size_t)(kb * 16 + half * 8) * NPIX + (ok ? iy * HW + ix : 0);
#pragma unroll
        for (int j = 0; j < 8; ++j)
            r[j] = ok ? src[(size_t)j * NPIX] : 0.f;
    };
    auto stsA = [&](const float* r, int buf) {
        uint4 v;
        v.x = bf2(r[0], r[1]); v.y = bf2(r[2], r[3]);
        v.z = bf2(r[4], r[5]); v.w = bf2(r[6], r[7]);
        *(uint4*)&A_s[buf][p][half * 8] = v;
    };
    auto stageB = [&](int c, int buf) {
        const __nv_bfloat16* base = wprep + (size_t)c * 3 * 16 * 128;
#pragma unroll
        for (int rep = 0; rep < 3; ++rep) {
            int idx = tid + rep * 256;
            int row = idx >> 4;
            int seg = idx & 15;
            int sp = row >> 4, k = row & 15;
            uint32_t d = smem_u32(&B_s[buf][sp][k][seg * 8]);
            cp_async16(d, base + ((size_t)row * 128 + seg * 8));
        }
    };

    auto mma_chunk = [&](int buf) {
        uint32_t a[2][4];
#pragma unroll
        for (int f = 0; f < 2; ++f) {
            uint32_t addr = smem_u32(&A_s[buf][wp + f * 16 + (lane & 15)][(lane >> 4) * 8]);
            asm volatile("ldmatrix.sync.aligned.m8n8.x4.shared.b16 {%0,%1,%2,%3}, [%4];"
                         : "=r"(a[f][0]), "=r"(a[f][1]), "=r"(a[f][2]), "=r"(a[f][3])
                         : "r"(addr));
        }
#pragma unroll
        for (int sp = 0; sp < 3; ++sp) {
#pragma unroll
            for (int og = 0; og < 4; ++og) {
                uint32_t baddr = smem_u32(&B_s[buf][sp][lane & 15][wo + og * 16 + ((lane >> 4) << 3)]);
                uint32_t b0, b1, b2, b3;
                asm volatile("ldmatrix.sync.aligned.m8n8.x4.trans.shared.b16 {%0,%1,%2,%3}, [%4];"
                             : "=r"(b0), "=r"(b1), "=r"(b2), "=r"(b3) : "r"(baddr));
#pragma unroll
                for (int f = 0; f < 2; ++f) {
                    MMA_BF16(acc[f][og * 2    ], a[f], b0, b1);
                    MMA_BF16(acc[f][og * 2 + 1], a[f], b2, b3);
                }
            }
        }
    };

    float ar[8];
    stageB(0, 0); cp_commit();
    ldgA(0, ar);
    stsA(ar, 0);
    cp_wait0();
    __syncthreads();

    for (int c = 0; c < NCH; ++c) {
        int buf = c & 1;
        if (c + 1 < NCH) {
            stageB(c + 1, buf ^ 1); cp_commit();
            ldgA(c + 1, ar);
        }
        mma_chunk(buf);
        if (c + 1 < NCH) {
            stsA(ar, buf ^ 1);
            cp_wait0();
        }
        __syncthreads();
    }

    const int q  = lane >> 2;
    const int cc = (lane & 3) * 2;
    float* outimg = out + (size_t)img * C2_OUT * NPIX;
#pragma unroll
    for (int f = 0; f < 2; ++f) {
        int pix = tile * 128 + wp + f * 16 + q;
#pragma unroll
        for (int of = 0; of < 8; ++of) {
            int oc = wo + of * 8 + cc;
            float bv0 = bias[oc], bv1 = bias[oc + 1];
            outimg[(size_t)oc * NPIX + pix]           = acc[f][of][0] + bv0;
            outimg[(size_t)(oc + 1) * NPIX + pix]     = acc[f][of][1] + bv1;
            outimg[(size_t)oc * NPIX + pix + 8]       = acc[f][of][2] + bv0;
            outimg[(size_t)(oc + 1) * NPIX + pix + 8] = acc[f][of][3] + bv1;
        }
    }
}

// ======================================================================
// fc1 GEMM via mma.sync bf16 — R8 shape; KSPLIT=16 (K slice = 512, NCH=32)
// for full-chip occupancy (256 CTAs).
// ======================================================================
__global__ void __launch_bounds__(256)
fc1_mma_kernel(const __nv_bfloat16* __restrict__ wprep)
{
    constexpr int NCH = FC1_IN / 16 / KSPLIT;   // 32

    __shared__ __nv_bfloat16 A_s[2][128][24];
    __shared__ __nv_bfloat16 B_s[2][3][16][136];

    const int tid  = threadIdx.x;
    const int wid  = tid >> 5;
    const int lane = tid & 31;
    const int ot   = blockIdx.x;
    const int rt   = blockIdx.y;
    const int ks   = blockIdx.z;
    const int wp   = (wid & 3) * 32;
    const int wo   = (wid >> 2) * 64;

    const int p    = tid >> 1;
    const int half = tid & 1;
    const int row  = rt * 128 + p;

    float acc[2][8][4];
#pragma unroll
    for (int i = 0; i < 2; ++i)
#pragma unroll
        for (int j = 0; j < 8; ++j)
#pragma unroll
            for (int q = 0; q < 4; ++q) acc[i][j][q] = 0.f;

    auto ldgA = [&](int c, float* r) {
        const float* src = &g_s3p_all[(size_t)row * FC1_IN + (ks * NCH + c) * 16 + half * 8];
        float4 v0 = *(const float4*)src;
        float4 v1 = *(const float4*)(src + 4);
        r[0] = v0.x; r[1] = v0.y; r[2] = v0.z; r[3] = v0.w;
        r[4] = v1.x; r[5] = v1.y; r[6] = v1.z; r[7] = v1.w;
    };
    auto stsA = [&](const float* r, int buf) {
        uint4 v;
        v.x = bf2(r[0], r[1]); v.y = bf2(r[2], r[3]);
        v.z = bf2(r[4], r[5]); v.w = bf2(r[6], r[7]);
        *(uint4*)&A_s[buf][p][half * 8] = v;
    };
    auto stageB = [&](int c, int buf) {
        const __nv_bfloat16* base = wprep + (size_t)(ot * 512 + ks * NCH + c) * 3 * 16 * 128;
#pragma unroll
        for (int rep = 0; rep < 3; ++rep) {
            int idx = tid + rep * 256;
            int rowk = idx >> 4;
            int seg  = idx & 15;
            int sp = rowk >> 4, k = rowk & 15;
            uint32_t d = smem_u32(&B_s[buf][sp][k][seg * 8]);
            cp_async16(d, base + ((size_t)rowk * 128 + seg * 8));
        }
    };

    auto mma_chunk = [&](int buf) {
        uint32_t a[2][4];
#pragma unroll
        for (int f = 0; f < 2; ++f) {
            uint32_t addr = smem_u32(&A_s[buf][wp + f * 16 + (lane & 15)][(lane >> 4) * 8]);
            asm volatile("ldmatrix.sync.aligned.m8n8.x4.shared.b16 {%0,%1,%2,%3}, [%4];"
                         : "=r"(a[f][0]), "=r"(a[f][1]), "=r"(a[f][2]), "=r"(a[f][3])
                         : "r"(addr));
        }
#pragma unroll
        for (int sp = 0; sp < 3; ++sp) {
#pragma unroll
            for (int og = 0; og < 4; ++og) {
                uint32_t baddr = smem_u32(&B_s[buf][sp][lane & 15][wo + og * 16 + ((lane >> 4) << 3)]);
                uint32_t b0, b1, b2, b3;
                asm volatile("ldmatrix.sync.aligned.m8n8.x4.trans.shared.b16 {%0,%1,%2,%3}, [%4];"
                             : "=r"(b0), "=r"(b1), "=r"(b2), "=r"(b3) : "r"(baddr));
#pragma unroll
                for (int f = 0; f < 2; ++f) {
                    MMA_BF16(acc[f][og * 2    ], a[f], b0, b1);
                    MMA_BF16(acc[f][og * 2 + 1], a[f], b2, b3);
                }
            }
        }
    };

    float ar[8];
    stageB(0, 0); cp_commit();
    ldgA(0, ar);
    stsA(ar, 0);
    cp_wait0();
    __syncthreads();

    for (int c = 0; c < NCH; ++c) {
        int buf = c & 1;
        if (c + 1 < NCH) {
            stageB(c + 1, buf ^ 1); cp_commit();
            ldgA(c + 1, ar);
        }
        mma_chunk(buf);
        if (c + 1 < NCH) {
            stsA(ar, buf ^ 1);
            cp_wait0();
        }
        __syncthreads();
    }

    const int q  = lane >> 2;
    const int cc = (lane & 3) * 2;
#pragma unroll
    for (int f = 0; f < 2; ++f) {
        int r0 = rt * 128 + wp + f * 16 + q;
#pragma unroll
        for (int of = 0; of < 8; ++of) {
            int o = ot * 128 + wo + of * 8 + cc;
            g_part[((size_t)ks * ROWS + r0    ) * FC1_OUT + o    ] = acc[f][of][0];
            g_part[((size_t)ks * ROWS + r0    ) * FC1_OUT + o + 1] = acc[f][of][1];
            g_part[((size_t)ks * ROWS + r0 + 8) * FC1_OUT + o    ] = acc[f][of][2];
            g_part[((size_t)ks * ROWS + r0 + 8) * FC1_OUT + o + 1] = acc[f][of][3];
        }
    }
}

// ======================================================================
// conv1 (tiny, 3 input ch): FFMA2 pipelined conv
// ======================================================================
template<int CIN, int HW, int GB, int ICB>
__global__ void __launch_bounds__(GB*(HW/2)*(HW/2))
conv3x3_pipe(const float* __restrict__ in,
             const float* __restrict__ wt,
             const float* __restrict__ bias,
             float* __restrict__ out,
             int Cout)
{
    constexpr int TP    = HW / 2;
    constexpr int TSUB  = TP * TP;
    constexpr int NT    = GB * TSUB;
    constexpr int TW    = HW + 2;
    constexpr int TS    = TW * TW;
    constexpr int OCT   = 8;
    constexpr int NST   = CIN / ICB;
    constexpr int LSLOT = (TS + TSUB - 1) / TSUB;
    constexpr int WTOT  = ICB * OCT * 9;
    constexpr int WSLOT = (WTOT + NT - 1) / NT;

    __shared__ float tile[2][ICB][GB][TS];
    __shared__ u64   ws  [2][ICB][OCT * 9];

    const int tid = threadIdx.x;
    const int sub = tid / TSUB;
    const int st  = tid % TSUB;
    const int b   = blockIdx.y * GB + sub;
    const int ocb = blockIdx.x * OCT;
    const int ty  = (st / TP) * 2;
    const int tx  = (st % TP) * 2;

    const float* inb = in + (size_t)b * CIN * HW * HW;

    int l_soff[LSLOT], l_goff[LSLOT], l_size[LSLOT];
#pragma unroll
    for (int k = 0; k < LSLOT; ++k) {
        int i = st + k * TSUB;
        int r = i / TW - 1, c = i % TW - 1;
        bool live = (i < TS);
        bool inb_ = live && r >= 0 && r < HW && c >= 0 && c < HW;
        l_soff[k] = live ? i : -1;
        l_goff[k] = inb_ ? (r * HW + c) : 0;
        l_size[k] = inb_ ? 4 : 0;
    }

    float wreg[WSLOT];

    auto issue_loads = [&](int s, int buf) {
#pragma unroll
        for (int ic = 0; ic < ICB; ++ic) {
            const float* src = inb + (size_t)(s * ICB + ic) * HW * HW;
#pragma unroll
            for (int k = 0; k < LSLOT; ++k) {
                if (l_soff[k] >= 0) {
                    uint32_t d = smem_u32(&tile[buf][ic][sub][l_soff[k]]);
                    cp_async4(d, src + l_goff[k], l_size[k]);
                }
            }
        }
    };
    auto load_w = [&](int s) {
#pragma unroll
        for (int j = 0; j < WSLOT; ++j) {
            int i = tid + j * NT;
            if (i < WTOT) {
                int ic = i / (OCT * 9), rem = i % (OCT * 9);
                int o = rem / 9, k = rem % 9;
                wreg[j] = wt[((size_t)(ocb + o) * CIN + s * ICB + ic) * 9 + k];
            }
        }
    };
    auto store_w = [&](int buf) {
#pragma unroll
        for (int j = 0; j < WSLOT; ++j) {
            int i = tid + j * NT;
            if (i < WTOT) {
                int ic = i / (OCT * 9), rem = i % (OCT * 9);
                ws[buf][ic][rem] = pack2(wreg[j], wreg[j]);
            }
        }
    };

    u64 pa[OCT][2];
#pragma unroll
    for (int o = 0; o < OCT; ++o) { pa[o][0] = 0ull; pa[o][1] = 0ull; }

    auto compute = [&](int buf) {
#pragma unroll
        for (int ic = 0; ic < ICB; ++ic) {
            const float* tp = &tile[buf][ic][sub][0];
            float r[4][4];
#pragma unroll
            for (int dy = 0; dy < 4; ++dy)
#pragma unroll
                for (int dx = 0; dx < 4; ++dx)
                    r[dy][dx] = tp[(ty + dy) * TW + tx + dx];
            u64 pr[4][3];
#pragma unroll
            for (int dy = 0; dy < 4; ++dy)
#pragma unroll
                for (int kx = 0; kx < 3; ++kx)
                    pr[dy][kx] = pack2(r[dy][kx], r[dy][kx + 1]);
#pragma unroll
            for (int o = 0; o < OCT; ++o) {
                const u64* w9 = &ws[buf][ic][o * 9];
#pragma unroll
                for (int ky = 0; ky < 3; ++ky) {
                    u64 w0 = w9[ky * 3 + 0], w1 = w9[ky * 3 + 1], w2 = w9[ky * 3 + 2];
                    ffma2(pa[o][0], pr[ky    ][0], w0);
                    ffma2(pa[o][0], pr[ky    ][1], w1);
                    ffma2(pa[o][0], pr[ky    ][2], w2);
                    ffma2(pa[o][1], pr[ky + 1][0], w0);
                    ffma2(pa[o][1], pr[ky + 1][1], w1);
                    ffma2(pa[o][1], pr[ky + 1][2], w2);
                }
            }
        }
    };

    load_w(0); store_w(0);
    issue_loads(0, 0);
    cp_commit(); cp_wait0();
    __syncthreads();

#pragma unroll 2
    for (int s = 0; s < NST; ++s) {
        int buf = s & 1;
        if (s + 1 < NST) { issue_loads(s + 1, buf ^ 1); cp_commit(); load_w(s + 1); }
        compute(buf);
        if (s + 1 < NST) { cp_wait0(); store_w(buf ^ 1); }
        __syncthreads();
    }

#pragma unroll
    for (int o = 0; o < OCT; ++o) {
        float bv = bias[ocb + o];
        u64 bp = pack2(bv, bv);
        u64 r0 = add2(pa[o][0], bp);
        u64 r1 = add2(pa[o][1], bp);
        float* dst = out + (((size_t)b * Cout + ocb + o) * HW + ty) * HW + tx;
        *(u64*)(dst)      = r0;
        *(u64*)(dst + HW) = r1;
    }
}

// ---------------- LIF / pool / fc kernels ----------------
__global__ void lif1_all_kernel(const float* __restrict__ mask_f1)
{
    int i = blockIdx.x * blockDim.x + threadIdx.x;
    if (i >= N1) return;
    float x = g_conv1out[i];
    float mk = mask_f1[i];
    float m = 0.f;
#pragma unroll
    for (int t = 0; t < TSTEPS; ++t) {
        m += x;
        float sp = (m >= 1.f) ? 1.f : 0.f;
        m -= sp;
        g_s1t[(size_t)t * N1 + i] = sp * mk;
    }
}

__global__ void lif2pool_all_kernel()
{
    int idx = blockIdx.x * blockDim.x + threadIdx.x;
    if (idx >= B * C2_OUT * H3 * H3) return;
    int px = idx & 15;
    int py = (idx >> 4) & 15;
    int c  = (idx >> 8) & 127;
    int b  = idx >> 15;
    const size_t chanstride = (size_t)B * C2_OUT * H1 * H1;
    size_t base  = ((size_t)b * C2_OUT + c) * (H1 * H1) + (2 * py) * H1 + 2 * px;
    size_t obase = ((size_t)b * C2_OUT + c) * (H3 * H3) + py * H3 + px;
    float m0 = 0.f, m1 = 0.f, m2v = 0.f, m3v = 0.f;
#pragma unroll
    for (int t = 0; t < TSTEPS; ++t) {
        float2 a  = *(const float2*)&g_conv2out_all[base + (size_t)t * chanstride];
        float2 bq = *(const float2*)&g_conv2out_all[base + H1 + (size_t)t * chanstride];
        m0 += a.x;   float s0 = (m0 >= 1.f) ? 1.f : 0.f;  m0 -= s0;
        m1 += a.y;   float s1 = (m1 >= 1.f) ? 1.f : 0.f;  m1 -= s1;
        m2v += bq.x; float s2 = (m2v >= 1.f) ? 1.f : 0.f; m2v -= s2;
        m3v += bq.y; float s3 = (m3v >= 1.f) ? 1.f : 0.f; m3v -= s3;
        g_s2p_all[obase + (size_t)t * (B * C2_OUT * H3 * H3)] = (s0 + s1 + s2 + s3) * 0.25f;
    }
}

__global__ void lif3maskpool_all_kernel(const float* __restrict__ mask_f2)
{
    int idx = blockIdx.x * blockDim.x + threadIdx.x;
    if (idx >= B * C2_OUT * 8 * 8) return;
    int px = idx & 7;
    int py = (idx >> 3) & 7;
    int c  = (idx >> 6) & 127;
    int b  = idx >> 13;
    const size_t slab = (size_t)B * C2_OUT * H3 * H3;
    size_t base  = ((size_t)b * C2_OUT + c) * (H3 * H3) + (2 * py) * H3 + 2 * px;
    size_t obase = ((size_t)b * C2_OUT + c) * 64 + py * 8 + px;
    float2 mka = *(const float2*)&mask_f2[base];
    float2 mkb = *(const float2*)&mask_f2[base + H3];
    float m0 = 0.f, m1 = 0.f, m2v = 0.f, m3v = 0.f;
#pragma unroll
    for (int t = 0; t < TSTEPS; ++t) {
        float2 a  = *(const float2*)&g_conv3out_all[base + (size_t)t * slab];
        float2 bq = *(const float2*)&g_conv3out_all[base + H3 + (size_t)t * slab];
        m0 += a.x;   float s0 = (m0 >= 1.f) ? 1.f : 0.f;  m0 -= s0;
        m1 += a.y;   float s1 = (m1 >= 1.f) ? 1.f : 0.f;  m1 -= s1;
        m2v += bq.x; float s2 = (m2v >= 1.f) ? 1.f : 0.f; m2v -= s2;
        m3v += bq.y; float s3 = (m3v >= 1.f) ? 1.f : 0.f; m3v -= s3;
        g_s3p_all[obase + (size_t)t * (B * FC1_IN)] =
            (s0 * mka.x + s1 * mka.y + s2 * mkb.x + s3 * mkb.y) * 0.25f;
    }
}

__global__ void fc1_chain_kernel(const float* __restrict__ fc1_b,
                                 const float* __restrict__ mask_c1)
{
    int idx = blockIdx.x * blockDim.x + threadIdx.x;
    if (idx >= B * FC1_OUT) return;
    int b = idx >> 10, o = idx & 1023;
    float mk = mask_c1[idx];
    float bias = fc1_b[o];
    float m = 0.f;
#pragma unroll
    for (int t = 0; t < TSTEPS; ++t) {
        int row = t * B + b;
        float sum = bias;
#pragma unroll
        for (int ks = 0; ks < KSPLIT; ++ks)
            sum += g_part[((size_t)ks * ROWS + row) * FC1_OUT + o];
        m += sum;
        float sp = (m >= 1.f) ? 1.f : 0.f;
        m -= sp;
        g_sfc1_all[(size_t)row * FC1_OUT + o] = sp * mk;
    }
}

__global__ void fc2_all_kernel(const float* __restrict__ w)
{
    int gw   = (blockIdx.x * blockDim.x + threadIdx.x) >> 5;
    int lane = threadIdx.x & 31;
    if (gw >= ROWS * FC2_OUT) return;
    int row = gw / FC2_OUT, o = gw % FC2_OUT;
    const float* sr = g_sfc1_all + (size_t)row * FC1_OUT;
    const float* wr = w + (size_t)o * FC1_OUT;
    float acc = 0.f;
#pragma unroll 8
    for (int k = lane; k < FC1_OUT; k += 32)
        acc += sr[k] * wr[k];
#pragma unroll
    for (int off = 16; off; off >>= 1)
        acc += __shfl_down_sync(0xFFFFFFFFu, acc, off);
    if (lane == 0)
        g_fc2out[row * FC2_OUT + o] = acc;
}

__global__ void fc2_chain_kernel(const float* __restrict__ fc2_b,
                                 float* __restrict__ c2)
{
    int idx = threadIdx.x;
    if (idx >= B * FC2_OUT) return;
    int b = idx / FC2_OUT, o = idx % FC2_OUT;
    float bias = fc2_b[o];
    float m = 0.f;
#pragma unroll
    for (int t = 0; t < TSTEPS; ++t) {
        m += g_fc2out[(t * B + b) * FC2_OUT + o] + bias;
        float sp = (m >= 1.f) ? 1.f : 0.f;
        m -= sp;
    }
    c2[idx] = m;
}

// ---------------- host launcher ----------------
extern "C" void kernel_launch(void* const* d_in, const int* in_sizes, int n_in,
                              void* d_out, int out_size)
{
    const float* X       = (const float*)d_in[0];
    const float* conv1_w = (const float*)d_in[1];
    const float* conv1_b = (const float*)d_in[2];
    const float* conv2_w = (const float*)d_in[3];
    const float* conv2_b = (const float*)d_in[4];
    const float* conv3_w = (const float*)d_in[5];
    const float* conv3_b = (const float*)d_in[6];
    const float* fc1_w   = (const float*)d_in[7];
    const float* fc1_b   = (const float*)d_in[8];
    const float* fc2_w   = (const float*)d_in[9];
    const float* fc2_b   = (const float*)d_in[10];
    const float* mask_f1 = (const float*)d_in[11];
    const float* mask_f2 = (const float*)d_in[12];
    const float* mask_c1 = (const float*)d_in[13];

    float* c2 = (float*)d_out;

    float *conv1out, *s1t, *conv2out, *s2p, *conv3out;
    __nv_bfloat16 *w2b, *w3b, *w1b;
    cudaGetSymbolAddress((void**)&conv1out, g_conv1out);
    cudaGetSymbolAddress((void**)&s1t,      g_s1t);
    cudaGetSymbolAddress((void**)&conv2out, g_conv2out_all);
    cudaGetSymbolAddress((void**)&s2p,      g_s2p_all);
    cudaGetSymbolAddress((void**)&conv3out, g_conv3out_all);
    cudaGetSymbolAddress((void**)&w2b,      g_w2b);
    cudaGetSymbolAddress((void**)&w3b,      g_w3b);
    cudaGetSymbolAddress((void**)&w1b,      g_w1b);

    // weight preps
    prep_w_bf16<C1_OUT><<<(C1_OUT * 9 * 128 + 255) / 256, 256>>>(conv2_w, w2b);
    prep_w_bf16<C2_OUT><<<(C2_OUT * 9 * 128 + 255) / 256, 256>>>(conv3_w, w3b);
    prep_fc1_bf16<<<8 * 512, 256>>>(fc1_w, w1b);

    // layer 1: conv once, LIF over all timesteps once
    conv3x3_pipe<3, H1, 1, 1><<<dim3(C1_OUT / 8, B), 256>>>(X, conv1_w, conv1_b, conv1out, C1_OUT);
    lif1_all_kernel<<<(N1 + 255) / 256, 256>>>(mask_f1);

    // layer 2: tensor-core conv (8 pixel-tiles per 1024-pixel image)
    conv_mma_kernel<C1_OUT, H1><<<dim3(8, ROWS), 256>>>(s1t, w2b, conv2_b, conv2out);
    lif2pool_all_kernel<<<(B * C2_OUT * H3 * H3 + 255) / 256, 256>>>();

    // layer 3: tensor-core conv (2 pixel-tiles per 256-pixel image)
    conv_mma_kernel<C2_OUT, H3><<<dim3(2, ROWS), 256>>>(s2p, w3b, conv3_b, conv3out);
    lif3maskpool_all_kernel<<<(B * C2_OUT * 8 * 8 + 255) / 256, 256>>>(mask_f2);

    // fc1 + fc2 (fc1 now KSPLIT=16 -> 256 CTAs, full-chip)
    fc1_mma_kernel<<<dim3(8, 2, KSPLIT), 256>>>(w1b);
    fc1_chain_kernel<<<(B * FC1_OUT + 255) / 256, 256>>>(fc1_b, mask_c1);
    fc2_all_kernel<<<(ROWS * FC2_OUT * 32 + 255) / 256, 256>>>(fc2_w);
    fc2_chain_kernel<<<1, 512>>>(fc2_b, c2);
}